// round 1
// baseline (speedup 1.0000x reference)
#include <cuda_runtime.h>
#include <math.h>

#define NENT 150000
#define NRELN 500
#define HD 128
#define DEG 32
#define TOPK 10

// -------- scratch (device globals; no allocation allowed) --------
__device__ float g_hnode[150016 * 128];
__device__ float g_neigh[150016 * 128];
__device__ float g_hrel[512 * 128];
__device__ float g_ssrc[150016];
__device__ float g_sdst[150016];
__device__ float g_srel[512];

// ---------------------------------------------------------------
// GEMM: C[M,128] = A[M,128] * B[128,128].  EPI: 0=none, 1=tanh
// Block: 256 threads, tile 128 rows x 128 cols, full K in smem.
// tx (0..31) -> 4 cols, ty (0..7) -> 16 rows.
// ---------------------------------------------------------------
template <int EPI>
__global__ void __launch_bounds__(256) gemm128(const float* __restrict__ A,
                                               const float* __restrict__ B,
                                               float* __restrict__ C, int M)
{
    extern __shared__ float smem[];
    float* As = smem;             // [128][128]
    float* Bs = smem + 128 * 128; // [128][128]

    const int tid = threadIdx.x;
    const int tx = tid & 31;
    const int ty = tid >> 5;
    const int row0 = blockIdx.x * 128;

    // load tiles (float4, fully coalesced: each warp covers one 512B row)
#pragma unroll
    for (int it = 0; it < 16; ++it) {
        int fi = tid + it * 256;     // float4 index 0..4095
        int r = fi >> 5;
        int c = (fi & 31) << 2;
        float4 av = make_float4(0.f, 0.f, 0.f, 0.f);
        int gr = row0 + r;
        if (gr < M) av = *reinterpret_cast<const float4*>(A + (size_t)gr * HD + c);
        *reinterpret_cast<float4*>(As + r * HD + c) = av;
        float4 bv = *reinterpret_cast<const float4*>(B + r * HD + c);
        *reinterpret_cast<float4*>(Bs + r * HD + c) = bv;
    }
    __syncthreads();

    float acc[16][4];
#pragma unroll
    for (int i = 0; i < 16; ++i) {
        acc[i][0] = 0.f; acc[i][1] = 0.f; acc[i][2] = 0.f; acc[i][3] = 0.f;
    }

#pragma unroll 4
    for (int k = 0; k < 128; ++k) {
        float4 b = *reinterpret_cast<const float4*>(Bs + k * HD + tx * 4);
#pragma unroll
        for (int i = 0; i < 16; ++i) {
            float a = As[(ty * 16 + i) * HD + k];   // warp-uniform row -> broadcast
            acc[i][0] += a * b.x;
            acc[i][1] += a * b.y;
            acc[i][2] += a * b.z;
            acc[i][3] += a * b.w;
        }
    }

#pragma unroll
    for (int i = 0; i < 16; ++i) {
        int gr = row0 + ty * 16 + i;
        if (gr < M) {
            float4 v;
            if (EPI == 1) {
                v.x = tanhf(acc[i][0]); v.y = tanhf(acc[i][1]);
                v.z = tanhf(acc[i][2]); v.w = tanhf(acc[i][3]);
            } else {
                v.x = acc[i][0]; v.y = acc[i][1]; v.z = acc[i][2]; v.w = acc[i][3];
            }
            *reinterpret_cast<float4*>(C + (size_t)gr * HD + tx * 4) = v;
        }
    }
}

// ---------------------------------------------------------------
// Score vectors: warp per row.
//   warps [0, NENT):      s_src = h_node . a1 ; s_dst = h_node . a2
//   warps [NENT, +NRELN): s_rel = h_rel  . a3
// ---------------------------------------------------------------
__global__ void __launch_bounds__(256) scores_kernel(const float* __restrict__ a)
{
    int warp = (blockIdx.x * blockDim.x + threadIdx.x) >> 5;
    int lane = threadIdx.x & 31;
    if (warp >= NENT + NRELN) return;

    if (warp < NENT) {
        float4 h  = *reinterpret_cast<const float4*>(g_hnode + (size_t)warp * HD + lane * 4);
        float4 a1 = *reinterpret_cast<const float4*>(a + lane * 4);
        float4 a2 = *reinterpret_cast<const float4*>(a + HD + lane * 4);
        float p1 = h.x * a1.x + h.y * a1.y + h.z * a1.z + h.w * a1.w;
        float p2 = h.x * a2.x + h.y * a2.y + h.z * a2.z + h.w * a2.w;
#pragma unroll
        for (int o = 16; o; o >>= 1) {
            p1 += __shfl_xor_sync(0xffffffffu, p1, o);
            p2 += __shfl_xor_sync(0xffffffffu, p2, o);
        }
        if (lane == 0) { g_ssrc[warp] = p1; g_sdst[warp] = p2; }
    } else {
        int r = warp - NENT;
        float4 h  = *reinterpret_cast<const float4*>(g_hrel + (size_t)r * HD + lane * 4);
        float4 a3 = *reinterpret_cast<const float4*>(a + 2 * HD + lane * 4);
        float p = h.x * a3.x + h.y * a3.y + h.z * a3.z + h.w * a3.w;
#pragma unroll
        for (int o = 16; o; o >>= 1) p += __shfl_xor_sync(0xffffffffu, p, o);
        if (lane == 0) g_srel[r] = p;
    }
}

// ---------------------------------------------------------------
// Attention: warp per node.
//  score/top-k: lane = neighbor (DEG==32)
//  gather-accumulate: lane = 4 output dims (float4), k = selected neighbor
// ---------------------------------------------------------------
__global__ void __launch_bounds__(256) attn_kernel(const int* __restrict__ src,
                                                   const int* __restrict__ relid)
{
    int warp = (blockIdx.x * blockDim.x + threadIdx.x) >> 5;
    int lane = threadIdx.x & 31;
    if (warp >= NENT) return;
    const int n = warp;

    int s_id = src[(size_t)n * DEG + lane];
    int r_id = relid[(size_t)n * DEG + lane];
    float sd = g_sdst[n];
    float sc = g_ssrc[s_id] + sd + g_srel[r_id];
    sc = sc > 0.f ? sc : 0.2f * sc;       // leaky_relu(., 0.2)

    // top-10 via iterative warp argmax (lowest-index tie-break, like lax.top_k)
    float val = sc;
    float my_e = 0.f;
    int my_d = 0;
#pragma unroll
    for (int t = 0; t < TOPK; ++t) {
        float v = val;
        int idx = lane;
#pragma unroll
        for (int o = 16; o; o >>= 1) {
            float ov = __shfl_xor_sync(0xffffffffu, v, o);
            int oi = __shfl_xor_sync(0xffffffffu, idx, o);
            if (ov > v || (ov == v && oi < idx)) { v = ov; idx = oi; }
        }
        if (lane == t) { my_e = v; my_d = idx; }
        if (lane == idx) val = -3.402823466e38f;
    }

    // softmax over the 10 selected (e[0] is the max)
    float m = __shfl_sync(0xffffffffu, my_e, 0);
    float p = (lane < TOPK) ? expf(my_e - m) : 0.f;
    float s = p;
#pragma unroll
    for (int o = 16; o; o >>= 1) s += __shfl_xor_sync(0xffffffffu, s, o);
    float attn = p / s;

    // lane k fetches its selected global src / rel ids
    int sel_s = __shfl_sync(0xffffffffu, s_id, my_d);
    int sel_r = __shfl_sync(0xffffffffu, r_id, my_d);

    float4 accv = make_float4(0.f, 0.f, 0.f, 0.f);
#pragma unroll
    for (int k = 0; k < TOPK; ++k) {
        float w = __shfl_sync(0xffffffffu, attn, k);
        int sk = __shfl_sync(0xffffffffu, sel_s, k);
        int rk = __shfl_sync(0xffffffffu, sel_r, k);
        float4 hv = *reinterpret_cast<const float4*>(g_hnode + (size_t)sk * HD + lane * 4);
        float4 rv = *reinterpret_cast<const float4*>(g_hrel + (size_t)rk * HD + lane * 4);
        accv.x += w * (hv.x + rv.x);
        accv.y += w * (hv.y + rv.y);
        accv.z += w * (hv.z + rv.z);
        accv.w += w * (hv.w + rv.w);
    }
    *reinterpret_cast<float4*>(g_neigh + (size_t)n * HD + lane * 4) = accv;
}

// ---------------------------------------------------------------
extern "C" void kernel_launch(void* const* d_in, const int* in_sizes, int n_in,
                              void* d_out, int out_size)
{
    const float* ent   = (const float*)d_in[0];
    const float* rel   = (const float*)d_in[1];
    const float* W     = (const float*)d_in[2];
    const float* Wr    = (const float*)d_in[3];
    const float* a     = (const float*)d_in[4];
    const float* nw    = (const float*)d_in[5];
    const int*   src   = (const int*)d_in[6];
    const int*   relid = (const int*)d_in[7];
    float* out = (float*)d_out;

    float *p_hnode, *p_hrel, *p_neigh;
    cudaGetSymbolAddress((void**)&p_hnode, g_hnode);
    cudaGetSymbolAddress((void**)&p_hrel, g_hrel);
    cudaGetSymbolAddress((void**)&p_neigh, g_neigh);

    const int SMEM = 2 * 128 * 128 * (int)sizeof(float); // 128 KB
    cudaFuncSetAttribute(gemm128<0>, cudaFuncAttributeMaxDynamicSharedMemorySize, SMEM);
    cudaFuncSetAttribute(gemm128<1>, cudaFuncAttributeMaxDynamicSharedMemorySize, SMEM);

    // h_node = ent_emb @ W
    gemm128<0><<<(NENT + 127) / 128, 256, SMEM>>>(ent, W, p_hnode, NENT);
    // h_rel = rel_emb @ W_r
    gemm128<0><<<(NRELN + 127) / 128, 256, SMEM>>>(rel, Wr, p_hrel, NRELN);
    // s_src, s_dst, s_rel
    {
        int warps = NENT + NRELN;
        int blocks = (warps * 32 + 255) / 256;
        scores_kernel<<<blocks, 256>>>(a);
    }
    // top-k attention + neighbor aggregation
    {
        int blocks = (NENT * 32 + 255) / 256;
        attn_kernel<<<blocks, 256>>>(src, relid);
    }
    // out = tanh(neigh @ neigh_w)
    gemm128<1><<<(NENT + 127) / 128, 256, SMEM>>>(p_neigh, nw, out, NENT);
}

// round 3
// speedup vs baseline: 1.6267x; 1.6267x over previous
#include <cuda_runtime.h>
#include <cuda_bf16.h>
#include <math.h>
#include <stdint.h>

#define NENT 150000
#define NRELN 500
#define HD 128
#define DEG 32
#define TOPK 10

// -------- scratch (device globals; no allocation allowed) --------
__device__ float g_hnode[150016 * 128];
__device__ float g_neigh[150016 * 128];
__device__ float g_hrel[512 * 128];
__device__ float g_ssrc[150016];
__device__ float g_sdst[150016];
__device__ float g_srel[512];
// pre-transposed + swizzled bf16-split weight images: [matrix][hi 32KB | lo 32KB]
__device__ __align__(16) unsigned char g_Bimg[3][65536];

// ================= helpers =================
__device__ __forceinline__ uint32_t smem_u32(const void* p) {
    uint32_t a;
    asm("{ .reg .u64 t; cvta.to.shared.u64 t, %1; cvt.u32.u64 %0, t; }" : "=r"(a) : "l"(p));
    return a;
}
__device__ __forceinline__ void ldsm_x4(uint32_t* r, uint32_t addr) {
    asm volatile("ldmatrix.sync.aligned.m8n8.x4.shared.b16 {%0,%1,%2,%3}, [%4];"
                 : "=r"(r[0]), "=r"(r[1]), "=r"(r[2]), "=r"(r[3]) : "r"(addr));
}
__device__ __forceinline__ void ldsm_x2(uint32_t* r, uint32_t addr) {
    asm volatile("ldmatrix.sync.aligned.m8n8.x2.shared.b16 {%0,%1}, [%2];"
                 : "=r"(r[0]), "=r"(r[1]) : "r"(addr));
}
__device__ __forceinline__ void mma_bf16(float* d, const uint32_t* a, uint32_t b0, uint32_t b1) {
    asm volatile(
        "mma.sync.aligned.m16n8k16.row.col.f32.bf16.bf16.f32 "
        "{%0,%1,%2,%3}, {%4,%5,%6,%7}, {%8,%9}, {%0,%1,%2,%3};"
        : "+f"(d[0]), "+f"(d[1]), "+f"(d[2]), "+f"(d[3])
        : "r"(a[0]), "r"(a[1]), "r"(a[2]), "r"(a[3]), "r"(b0), "r"(b1));
}
__device__ __forceinline__ void bf_split(float v, __nv_bfloat16& h, __nv_bfloat16& l) {
    h = __float2bfloat16(v);
    l = __float2bfloat16(v - __bfloat162float(h));
}
__device__ __forceinline__ uint32_t pack2(__nv_bfloat16 a, __nv_bfloat16 b) {
    __nv_bfloat162 t;
    t.x = a; t.y = b;
    return *reinterpret_cast<uint32_t*>(&t);
}
// tile layout: row-major rows of 128 bf16 (256B = 16 units of 16B), unit XOR-swizzled
// byte offset of (row, 16B-unit u): row*256 + ((u ^ (row&7))<<4)
__device__ __forceinline__ uint32_t img_off(int n, int k) {
    return (uint32_t)(n * 256 + ((((k >> 3) ^ (n & 7))) << 4) + (k & 7) * 2);
}

// ---------------------------------------------------------------
// prep: transposed + swizzled + bf16-split weight images.
// blockIdx 0=W, 1=W_r, 2=neigh_w.  image row n holds column n of M (k-major).
// ---------------------------------------------------------------
__global__ void __launch_bounds__(256) prep_kernel(const float* __restrict__ W,
                                                   const float* __restrict__ Wr,
                                                   const float* __restrict__ Nw) {
    const float* M = (blockIdx.x == 0) ? W : (blockIdx.x == 1) ? Wr : Nw;
    unsigned char* img = g_Bimg[blockIdx.x];
    for (int idx = threadIdx.x; idx < 128 * 128; idx += 256) {
        int k = idx >> 7, n = idx & 127;
        float v = M[idx];
        __nv_bfloat16 h, l;
        bf_split(v, h, l);
        uint32_t off = img_off(n, k);
        *reinterpret_cast<__nv_bfloat16*>(img + off) = h;
        *reinterpret_cast<__nv_bfloat16*>(img + 32768 + off) = l;
    }
}

// ---------------------------------------------------------------
// HMMA GEMM: C[M,128] = A[M,128] @ B (image).  bf16 3-term split.
// EPI: 1 = tanh; 2 = store + s1/s2 (a cols 0,1); 3 = store + s1 (a col 2)
// 256 threads; CTA tile 128x128, K=128 resident; warp tile 32x64.
// ---------------------------------------------------------------
template <int EPI>
__global__ void __launch_bounds__(256) gemm_hmma(const float* __restrict__ A,
                                                 const unsigned char* __restrict__ Bimg,
                                                 float* __restrict__ C, int M,
                                                 const float* __restrict__ avec,
                                                 float* __restrict__ s1,
                                                 float* __restrict__ s2) {
    extern __shared__ __align__(16) unsigned char dynsm[];
    __shared__ float sred1[128][2];
    __shared__ float sred2[128][2];

    const int tid = threadIdx.x;
    const int wid = tid >> 5;
    const int lane = tid & 31;
    const int row0 = blockIdx.x * 128;

    // ---- B: straight 64KB copy of pre-swizzled hi|lo image ----
    {
        const uint4* srcB = reinterpret_cast<const uint4*>(Bimg);
        uint4* dstB = reinterpret_cast<uint4*>(dynsm + 65536);
#pragma unroll
        for (int i = 0; i < 16; ++i) dstB[tid + i * 256] = srcB[tid + i * 256];
    }
    // ---- A: load fp32, split to bf16 hi/lo, swizzled store ----
#pragma unroll
    for (int it = 0; it < 8; ++it) {
        int idx = tid + it * 256;      // (row, 16B-unit)
        int r = idx >> 4;
        int u = idx & 15;
        int gr = row0 + r;
        float4 v0 = make_float4(0.f, 0.f, 0.f, 0.f);
        float4 v1 = v0;
        if (gr < M) {
            v0 = *reinterpret_cast<const float4*>(A + (size_t)gr * HD + u * 8);
            v1 = *reinterpret_cast<const float4*>(A + (size_t)gr * HD + u * 8 + 4);
        }
        __nv_bfloat16 h[8], l[8];
        bf_split(v0.x, h[0], l[0]); bf_split(v0.y, h[1], l[1]);
        bf_split(v0.z, h[2], l[2]); bf_split(v0.w, h[3], l[3]);
        bf_split(v1.x, h[4], l[4]); bf_split(v1.y, h[5], l[5]);
        bf_split(v1.z, h[6], l[6]); bf_split(v1.w, h[7], l[7]);
        uint32_t off = r * 256 + (((u ^ (r & 7))) << 4);
        *reinterpret_cast<uint4*>(dynsm + off) =
            make_uint4(pack2(h[0], h[1]), pack2(h[2], h[3]), pack2(h[4], h[5]), pack2(h[6], h[7]));
        *reinterpret_cast<uint4*>(dynsm + 32768 + off) =
            make_uint4(pack2(l[0], l[1]), pack2(l[2], l[3]), pack2(l[4], l[5]), pack2(l[6], l[7]));
    }
    __syncthreads();

    // ---- compute ----
    const uint32_t sb = smem_u32(dynsm);
    const uint32_t AH = sb, AL = sb + 32768, BH = sb + 65536, BL = sb + 98304;
    const int wr = wid >> 1;            // 0..3 : 32-row tile
    const int wc = wid & 1;             // 0..1 : 64-col tile
    const int r0w = wr * 32;
    const int c0w = wc * 64;

    const int rA = lane & 15;           // A ldmatrix row-in-tile per lane
    const int uA = lane >> 4;           // A k-half select
    const int axr = rA & 7;
    const int nB = lane & 7;            // B ldmatrix row per lane
    const int uB = (lane >> 3) & 1;

    uint32_t arow[2], brow[8];
#pragma unroll
    for (int rb = 0; rb < 2; ++rb) arow[rb] = (uint32_t)(r0w + rb * 16 + rA) * 256;
#pragma unroll
    for (int nb = 0; nb < 8; ++nb) brow[nb] = (uint32_t)(c0w + nb * 8 + nB) * 256;

    float acc[2][8][4];
#pragma unroll
    for (int rb = 0; rb < 2; ++rb)
#pragma unroll
        for (int nb = 0; nb < 8; ++nb) {
            acc[rb][nb][0] = 0.f; acc[rb][nb][1] = 0.f;
            acc[rb][nb][2] = 0.f; acc[rb][nb][3] = 0.f;
        }

#pragma unroll
    for (int kb = 0; kb < 8; ++kb) {
        uint32_t offA = (uint32_t)((2 * kb + uA) ^ axr) << 4;
        uint32_t offB = (uint32_t)((2 * kb + uB) ^ nB) << 4;
        uint32_t ah[2][4], al[2][4];
        ldsm_x4(ah[0], AH + arow[0] + offA);
        ldsm_x4(ah[1], AH + arow[1] + offA);
        ldsm_x4(al[0], AL + arow[0] + offA);
        ldsm_x4(al[1], AL + arow[1] + offA);
#pragma unroll
        for (int nb = 0; nb < 8; ++nb) {
            uint32_t bh[2], bl[2];
            ldsm_x2(bh, BH + brow[nb] + offB);
            ldsm_x2(bl, BL + brow[nb] + offB);
#pragma unroll
            for (int rb = 0; rb < 2; ++rb) {
                mma_bf16(acc[rb][nb], ah[rb], bh[0], bh[1]);
                mma_bf16(acc[rb][nb], al[rb], bh[0], bh[1]);
                mma_bf16(acc[rb][nb], ah[rb], bl[0], bl[1]);
            }
        }
    }

    // ---- epilogue: direct fragment stores (+ fused score dots) ----
    const int tg = lane >> 2, tig = lane & 3;
    float p1[4] = {0.f, 0.f, 0.f, 0.f};
    float p2[4] = {0.f, 0.f, 0.f, 0.f};

#pragma unroll
    for (int rb = 0; rb < 2; ++rb)
#pragma unroll
        for (int nb = 0; nb < 8; ++nb) {
            float* d = acc[rb][nb];
            int c = c0w + nb * 8 + tig * 2;
            if (EPI == 1) {
                d[0] = tanhf(d[0]); d[1] = tanhf(d[1]);
                d[2] = tanhf(d[2]); d[3] = tanhf(d[3]);
            }
            if (EPI == 2) {
                float a1x = avec[c], a1y = avec[c + 1];
                float a2x = avec[128 + c], a2y = avec[129 + c];
                p1[rb * 2]     += d[0] * a1x + d[1] * a1y;
                p2[rb * 2]     += d[0] * a2x + d[1] * a2y;
                p1[rb * 2 + 1] += d[2] * a1x + d[3] * a1y;
                p2[rb * 2 + 1] += d[2] * a2x + d[3] * a2y;
            }
            if (EPI == 3) {
                float a3x = avec[256 + c], a3y = avec[257 + c];
                p1[rb * 2]     += d[0] * a3x + d[1] * a3y;
                p1[rb * 2 + 1] += d[2] * a3x + d[3] * a3y;
            }
            int r1 = row0 + r0w + rb * 16 + tg;
            if (r1 < M)
                *reinterpret_cast<float2*>(C + (size_t)r1 * HD + c) = make_float2(d[0], d[1]);
            if (r1 + 8 < M)
                *reinterpret_cast<float2*>(C + (size_t)(r1 + 8) * HD + c) = make_float2(d[2], d[3]);
        }

    if (EPI >= 2) {
#pragma unroll
        for (int rs = 0; rs < 4; ++rs) {
            p1[rs] += __shfl_xor_sync(0xffffffffu, p1[rs], 1);
            p1[rs] += __shfl_xor_sync(0xffffffffu, p1[rs], 2);
            if (EPI == 2) {
                p2[rs] += __shfl_xor_sync(0xffffffffu, p2[rs], 1);
                p2[rs] += __shfl_xor_sync(0xffffffffu, p2[rs], 2);
            }
        }
        if (tig == 0) {
#pragma unroll
            for (int rs = 0; rs < 4; ++rs) {
                int rl = r0w + (rs >> 1) * 16 + (rs & 1) * 8 + tg;
                sred1[rl][wc] = p1[rs];
                if (EPI == 2) sred2[rl][wc] = p2[rs];
            }
        }
        __syncthreads();
        if (tid < 128 && row0 + tid < M) {
            s1[row0 + tid] = sred1[tid][0] + sred1[tid][1];
            if (EPI == 2) s2[row0 + tid] = sred2[tid][0] + sred2[tid][1];
        }
    }
}

// ---------------------------------------------------------------
// Attention: warp per node. Rank-based top-k (set selection only —
// softmax & weighted sum are permutation invariant).
// ---------------------------------------------------------------
__global__ void __launch_bounds__(256) attn_kernel(const int* __restrict__ src,
                                                   const int* __restrict__ relid) {
    __shared__ float ssc[8][32];
    int warp = (blockIdx.x * blockDim.x + threadIdx.x) >> 5;
    int w = threadIdx.x >> 5;
    int lane = threadIdx.x & 31;
    if (warp >= NENT) return;
    const int n = warp;

    int s_id = src[(size_t)n * DEG + lane];
    int r_id = relid[(size_t)n * DEG + lane];
    float sc = g_ssrc[s_id] + g_sdst[n] + g_srel[r_id];
    sc = sc > 0.f ? sc : 0.2f * sc;  // leaky_relu 0.2

    ssc[w][lane] = sc;
    __syncwarp();
    int rank = 0;
#pragma unroll
    for (int j = 0; j < 32; ++j) {
        float o = ssc[w][j];
        rank += (o > sc) || (o == sc && j < lane);
    }
    bool sel = rank < TOPK;

    float m = sc;
#pragma unroll
    for (int o = 16; o; o >>= 1) m = fmaxf(m, __shfl_xor_sync(0xffffffffu, m, o));
    float p = sel ? __expf(sc - m) : 0.f;
    float s = p;
#pragma unroll
    for (int o = 16; o; o >>= 1) s += __shfl_xor_sync(0xffffffffu, s, o);
    float attn = p / s;

    unsigned mask = __ballot_sync(0xffffffffu, sel);
    float4 acc = make_float4(0.f, 0.f, 0.f, 0.f);
#pragma unroll
    for (int k = 0; k < TOPK; ++k) {
        int l = __ffs(mask) - 1;
        mask &= mask - 1;
        float wgt = __shfl_sync(0xffffffffu, attn, l);
        int sk = __shfl_sync(0xffffffffu, s_id, l);
        int rk = __shfl_sync(0xffffffffu, r_id, l);
        float4 hv = *reinterpret_cast<const float4*>(g_hnode + (size_t)sk * HD + lane * 4);
        float4 rv = *reinterpret_cast<const float4*>(g_hrel + (size_t)rk * HD + lane * 4);
        acc.x += wgt * (hv.x + rv.x);
        acc.y += wgt * (hv.y + rv.y);
        acc.z += wgt * (hv.z + rv.z);
        acc.w += wgt * (hv.w + rv.w);
    }
    *reinterpret_cast<float4*>(g_neigh + (size_t)n * HD + lane * 4) = acc;
}

// ---------------------------------------------------------------
extern "C" void kernel_launch(void* const* d_in, const int* in_sizes, int n_in,
                              void* d_out, int out_size) {
    const float* ent   = (const float*)d_in[0];
    const float* rel   = (const float*)d_in[1];
    const float* W     = (const float*)d_in[2];
    const float* Wr    = (const float*)d_in[3];
    const float* a     = (const float*)d_in[4];
    const float* nw    = (const float*)d_in[5];
    const int*   src   = (const int*)d_in[6];
    const int*   relid = (const int*)d_in[7];
    float* out = (float*)d_out;

    float *p_hnode, *p_hrel, *p_neigh, *p_ssrc, *p_sdst, *p_srel;
    unsigned char* p_img;
    cudaGetSymbolAddress((void**)&p_hnode, g_hnode);
    cudaGetSymbolAddress((void**)&p_hrel, g_hrel);
    cudaGetSymbolAddress((void**)&p_neigh, g_neigh);
    cudaGetSymbolAddress((void**)&p_ssrc, g_ssrc);
    cudaGetSymbolAddress((void**)&p_sdst, g_sdst);
    cudaGetSymbolAddress((void**)&p_srel, g_srel);
    cudaGetSymbolAddress((void**)&p_img, g_Bimg);

    const int SMEM = 131072;
    cudaFuncSetAttribute(gemm_hmma<1>, cudaFuncAttributeMaxDynamicSharedMemorySize, SMEM);
    cudaFuncSetAttribute(gemm_hmma<2>, cudaFuncAttributeMaxDynamicSharedMemorySize, SMEM);
    cudaFuncSetAttribute(gemm_hmma<3>, cudaFuncAttributeMaxDynamicSharedMemorySize, SMEM);

    prep_kernel<<<3, 256>>>(W, Wr, nw);

    const int NB = (NENT + 127) / 128;
    // h_node = ent @ W  (+ fused s_src/s_dst)
    gemm_hmma<2><<<NB, 256, SMEM>>>(ent, p_img, p_hnode, NENT, a, p_ssrc, p_sdst);
    // h_rel = rel @ W_r (+ fused s_rel)
    gemm_hmma<3><<<(NRELN + 127) / 128, 256, SMEM>>>(rel, p_img + 65536, p_hrel, NRELN, a, p_srel, nullptr);
    // attention + aggregation
    attn_kernel<<<(NENT * 32 + 255) / 256, 256>>>(src, relid);
    // out = tanh(neigh @ neigh_w)
    gemm_hmma<1><<<NB, 256, SMEM>>>(p_neigh, p_img + 2 * 65536, out, NENT, nullptr, nullptr, nullptr);
}